// round 2
// baseline (speedup 1.0000x reference)
#include <cuda_runtime.h>
#include <math.h>

typedef unsigned long long ull;

#define Bdim 8192
#define Ddim 64
#define Odim 256
#define BT 128          // b-tile per block

// Projected centers: cproj[o][e] = sum_d betas[o][d][e] * centers[o][d]
__device__ float g_cproj[Odim * Ddim];

__global__ void cproj_kernel(const float* __restrict__ betas,
                             const float* __restrict__ centers) {
    int o = blockIdx.x;
    int e = threadIdx.x;
    const float* bo = betas + (size_t)o * Ddim * Ddim;
    const float* co = centers + (size_t)o * Ddim;
    float s = 0.f;
#pragma unroll 16
    for (int d = 0; d < Ddim; d++) s = fmaf(bo[d * Ddim + e], co[d], s);
    g_cproj[o * Ddim + e] = s;
}

__device__ __forceinline__ ull packdup(float v) {
    ull r;
    unsigned u = __float_as_uint(v);
    asm("mov.b64 %0, {%1, %1};" : "=l"(r) : "r"(u));
    return r;
}

__device__ __forceinline__ ull pack2(float a, float b) {
    ull r;
    asm("mov.b64 %0, {%1, %2};" : "=l"(r)
        : "r"(__float_as_uint(a)), "r"(__float_as_uint(b)));
    return r;
}

// packed dual-lane fp32 FMA: c.lo += a.lo*b.lo ; c.hi += a.hi*b.hi
__device__ __forceinline__ void ffma2(ull& c, ull a, ull b) {
    asm("fma.rn.f32x2 %0, %1, %2, %0;" : "+l"(c) : "l"(a), "l"(b));
}

// One block: one o, 128 consecutive b. 128 threads (4 warps):
//   lane -> 4 b's (4*lane .. 4*lane+3)
//   eg = tid>>5 -> e range [16*eg, 16*eg+16)  (warp-uniform -> betas LDS broadcast)
__global__ __launch_bounds__(128) void ebf_main(const float* __restrict__ x,
                                                const float* __restrict__ betas,
                                                float* __restrict__ out) {
    __shared__ __align__(16) float bs[Ddim * Ddim];   // 16 KB, betas[o] as [d][e]
    __shared__ __align__(16) float xs[Ddim * BT];     // 32 KB, x tile transposed [d][b]

    int tid = threadIdx.x;
    int o = blockIdx.y;
    int b0 = blockIdx.x * BT;
    int lane = tid & 31;
    int eg = tid >> 5;

    // --- load betas[o]: 4096 floats = 1024 float4, coalesced ---
    const float4* bg = (const float4*)(betas + (size_t)o * Ddim * Ddim);
    float4* bs4 = (float4*)bs;
#pragma unroll
    for (int i = 0; i < 8; i++) bs4[tid + i * 128] = bg[tid + i * 128];

    // --- load + transpose x tile: 128 b x 64 d = 2048 float4 ---
    const float4* xg = (const float4*)(x + (size_t)b0 * Ddim);
#pragma unroll
    for (int i = 0; i < 16; i++) {
        int idx4 = tid + i * 128;
        float4 v = xg[idx4];
        int bl = idx4 >> 4;          // local b row
        int d4 = (idx4 & 15) << 2;   // starting d
        xs[(d4 + 0) * BT + bl] = v.x;
        xs[(d4 + 1) * BT + bl] = v.y;
        xs[(d4 + 2) * BT + bl] = v.z;
        xs[(d4 + 3) * BT + bl] = v.w;
    }

    // --- init accumulators to -cproj: acc = sum(beta*x) - cproj; square is sign-free ---
    ull acc[4][8];   // [b][e-pair]
    {
        const float2* cp2 = (const float2*)(g_cproj + o * Ddim + eg * 16);
#pragma unroll
        for (int j = 0; j < 8; j++) {
            float2 c = cp2[j];
            ull cc = pack2(-c.x, -c.y);
            acc[0][j] = cc; acc[1][j] = cc; acc[2][j] = cc; acc[3][j] = cc;
        }
    }
    __syncthreads();

    const float4* xrow = (const float4*)xs + lane;                 // xs[d][4*lane]
    const ulonglong2* brow = (const ulonglong2*)(bs + eg * 16);    // bs[d][16*eg]

    // --- main loop: 64 d iters; per iter: 5 LDS, 32 FFMA2 ---
#pragma unroll 2
    for (int d = 0; d < Ddim; d++) {
        float4 xv = xrow[d * (BT / 4)];
        ull xd0 = packdup(xv.x), xd1 = packdup(xv.y),
            xd2 = packdup(xv.z), xd3 = packdup(xv.w);
        ulonglong2 p0 = brow[d * 16 + 0];
        ulonglong2 p1 = brow[d * 16 + 1];
        ulonglong2 p2 = brow[d * 16 + 2];
        ulonglong2 p3 = brow[d * 16 + 3];

        ffma2(acc[0][0], p0.x, xd0); ffma2(acc[0][1], p0.y, xd0);
        ffma2(acc[0][2], p1.x, xd0); ffma2(acc[0][3], p1.y, xd0);
        ffma2(acc[0][4], p2.x, xd0); ffma2(acc[0][5], p2.y, xd0);
        ffma2(acc[0][6], p3.x, xd0); ffma2(acc[0][7], p3.y, xd0);

        ffma2(acc[1][0], p0.x, xd1); ffma2(acc[1][1], p0.y, xd1);
        ffma2(acc[1][2], p1.x, xd1); ffma2(acc[1][3], p1.y, xd1);
        ffma2(acc[1][4], p2.x, xd1); ffma2(acc[1][5], p2.y, xd1);
        ffma2(acc[1][6], p3.x, xd1); ffma2(acc[1][7], p3.y, xd1);

        ffma2(acc[2][0], p0.x, xd2); ffma2(acc[2][1], p0.y, xd2);
        ffma2(acc[2][2], p1.x, xd2); ffma2(acc[2][3], p1.y, xd2);
        ffma2(acc[2][4], p2.x, xd2); ffma2(acc[2][5], p2.y, xd2);
        ffma2(acc[2][6], p3.x, xd2); ffma2(acc[2][7], p3.y, xd2);

        ffma2(acc[3][0], p0.x, xd3); ffma2(acc[3][1], p0.y, xd3);
        ffma2(acc[3][2], p1.x, xd3); ffma2(acc[3][3], p1.y, xd3);
        ffma2(acc[3][4], p2.x, xd3); ffma2(acc[3][5], p2.y, xd3);
        ffma2(acc[3][6], p3.x, xd3); ffma2(acc[3][7], p3.y, xd3);
    }

    // --- per-b square-reduce over this thread's 16 e's ---
    float q[4];
#pragma unroll
    for (int b = 0; b < 4; b++) {
        ull qq = 0;  // packed 0.0f pair
#pragma unroll
        for (int j = 0; j < 8; j++) ffma2(qq, acc[b][j], acc[b][j]);
        float2 qv = *(float2*)&qq;
        q[b] = qv.x + qv.y;
    }

    // --- cross-warp combine via smem (alias bs, done with betas) ---
    __syncthreads();
    float4* part4 = (float4*)bs;                    // part[eg][128] as float4
    part4[eg * 32 + lane] = make_float4(q[0], q[1], q[2], q[3]);
    __syncthreads();

    {
        float* part = bs;
        float s = part[0 * BT + tid] + part[1 * BT + tid]
                + part[2 * BT + tid] + part[3 * BT + tid];
        out[(size_t)(b0 + tid) * Odim + o] = expf(-s);
    }
}

extern "C" void kernel_launch(void* const* d_in, const int* in_sizes, int n_in,
                              void* d_out, int out_size) {
    const float* x       = (const float*)d_in[0];   // [8192, 64]
    const float* centers = (const float*)d_in[1];   // [256, 1, 64]
    const float* betas   = (const float*)d_in[2];   // [256, 64, 64]
    float* out = (float*)d_out;                     // [8192, 256]

    cproj_kernel<<<Odim, Ddim>>>(betas, centers);
    dim3 grid(Bdim / BT, Odim);
    ebf_main<<<grid, 128>>>(x, betas, out);
}

// round 7
// speedup vs baseline: 1.4802x; 1.4802x over previous
#include <cuda_runtime.h>
#include <math.h>

typedef unsigned long long ull;

#define Bdim 8192
#define Ddim 64
#define Odim 256
#define BT 128          // b-tile per block

// Projected centers: cproj[o][e] = sum_d betas[o][d][e] * centers[o][d]
__device__ float g_cproj[Odim * Ddim];
// Globally transposed x: xT[d][b]
__device__ float g_xT[Ddim * Bdim];

__global__ void cproj_kernel(const float* __restrict__ betas,
                             const float* __restrict__ centers) {
    int o = blockIdx.x;
    int e = threadIdx.x;
    const float* bo = betas + (size_t)o * Ddim * Ddim;
    const float* co = centers + (size_t)o * Ddim;
    float s = 0.f;
#pragma unroll 16
    for (int d = 0; d < Ddim; d++) s = fmaf(bo[d * Ddim + e], co[d], s);
    g_cproj[o * Ddim + e] = s;
}

// x[8192][64] -> g_xT[64][8192], standard 32x32 tile via padded smem
__global__ __launch_bounds__(256) void xpose_kernel(const float* __restrict__ x) {
    __shared__ float t[32][33];
    int tx = threadIdx.x & 31;
    int ty = threadIdx.x >> 5;          // 0..7
    int b0 = blockIdx.x * 32;
    int d0 = blockIdx.y * 32;
#pragma unroll
    for (int j = 0; j < 32; j += 8)
        t[ty + j][tx] = x[(size_t)(b0 + ty + j) * Ddim + d0 + tx];
    __syncthreads();
#pragma unroll
    for (int j = 0; j < 32; j += 8)
        g_xT[(size_t)(d0 + ty + j) * Bdim + b0 + tx] = t[tx][ty + j];
}

__device__ __forceinline__ ull packdup(float v) {
    ull r;
    unsigned u = __float_as_uint(v);
    asm("mov.b64 %0, {%1, %1};" : "=l"(r) : "r"(u));
    return r;
}

__device__ __forceinline__ ull pack2(float a, float b) {
    ull r;
    asm("mov.b64 %0, {%1, %2};" : "=l"(r)
        : "r"(__float_as_uint(a)), "r"(__float_as_uint(b)));
    return r;
}

// packed dual-lane fp32 FMA: c.lo += a.lo*b.lo ; c.hi += a.hi*b.hi
__device__ __forceinline__ void ffma2(ull& c, ull a, ull b) {
    asm("fma.rn.f32x2 %0, %1, %2, %0;" : "+l"(c) : "l"(a), "l"(b));
}

// One block: one o, 128 consecutive b. 256 threads (8 warps):
//   lane -> 4 b's (4*lane .. 4*lane+3)   -> one LDS.128 x read per iter
//   eg = tid>>5 -> e range [8*eg, 8*eg+8) (warp-uniform -> betas LDS broadcast)
__global__ __launch_bounds__(256) void ebf_main(const float* __restrict__ betas,
                                                float* __restrict__ out) {
    __shared__ __align__(16) float bs[Ddim * Ddim];   // 16 KB, betas[o] as [d][e]
    __shared__ __align__(16) float xs[Ddim * BT];     // 32 KB, x tile [d][b_local]

    int tid = threadIdx.x;
    int o = blockIdx.y;
    int b0 = blockIdx.x * BT;
    int lane = tid & 31;
    int eg = tid >> 5;

    // --- load betas[o]: 1024 float4, coalesced ---
    const float4* bg = (const float4*)(betas + (size_t)o * Ddim * Ddim);
    float4* bs4 = (float4*)bs;
#pragma unroll
    for (int i = 0; i < 4; i++) bs4[tid + i * 256] = bg[tid + i * 256];

    // --- load x tile from pre-transposed g_xT: rows are contiguous -> no conflicts ---
    const float4* xtg = (const float4*)g_xT;
    float4* xs4 = (float4*)xs;
#pragma unroll
    for (int i = 0; i < 8; i++) {
        int idx = tid + i * 256;
        int row = idx >> 5;            // d
        int col = idx & 31;            // float4 within the 128-b row
        xs4[idx] = xtg[row * (Bdim / 4) + (b0 >> 2) + col];
    }

    // --- init accumulators to -cproj (acc = sum(beta*x) - cproj; square is sign-free) ---
    ull acc[4][4];   // [b][e-pair]
    {
        const float2* cp2 = (const float2*)(g_cproj + o * Ddim + eg * 8);
#pragma unroll
        for (int j = 0; j < 4; j++) {
            float2 c = cp2[j];
            ull cc = pack2(-c.x, -c.y);
            acc[0][j] = cc; acc[1][j] = cc; acc[2][j] = cc; acc[3][j] = cc;
        }
    }
    __syncthreads();

    const float4* xrow = (const float4*)xs + lane;      // xs[d][4*lane]
    const ulonglong2* brow = (const ulonglong2*)bs;     // 16B granules of bs

    // --- main loop: 64 d iters; per warp-iter: 3 LDS, 16 FFMA2 ---
#pragma unroll 4
    for (int d = 0; d < Ddim; d++) {
        float4 xv = xrow[d * (BT / 4)];
        ull xd0 = packdup(xv.x), xd1 = packdup(xv.y),
            xd2 = packdup(xv.z), xd3 = packdup(xv.w);
        ulonglong2 p0 = brow[d * 16 + eg * 2];          // betas[d][8eg..8eg+3]
        ulonglong2 p1 = brow[d * 16 + eg * 2 + 1];      // betas[d][8eg+4..8eg+7]

        ffma2(acc[0][0], p0.x, xd0); ffma2(acc[0][1], p0.y, xd0);
        ffma2(acc[0][2], p1.x, xd0); ffma2(acc[0][3], p1.y, xd0);

        ffma2(acc[1][0], p0.x, xd1); ffma2(acc[1][1], p0.y, xd1);
        ffma2(acc[1][2], p1.x, xd1); ffma2(acc[1][3], p1.y, xd1);

        ffma2(acc[2][0], p0.x, xd2); ffma2(acc[2][1], p0.y, xd2);
        ffma2(acc[2][2], p1.x, xd2); ffma2(acc[2][3], p1.y, xd2);

        ffma2(acc[3][0], p0.x, xd3); ffma2(acc[3][1], p0.y, xd3);
        ffma2(acc[3][2], p1.x, xd3); ffma2(acc[3][3], p1.y, xd3);
    }

    // --- per-b square-reduce over this thread's 8 e's ---
    float q[4];
#pragma unroll
    for (int b = 0; b < 4; b++) {
        ull qq = 0;  // packed {0.0f, 0.0f}
#pragma unroll
        for (int j = 0; j < 4; j++) ffma2(qq, acc[b][j], acc[b][j]);
        float2 qv = *(float2*)&qq;
        q[b] = qv.x + qv.y;
    }

    // --- cross-warp combine via smem (alias bs; betas no longer needed) ---
    __syncthreads();
    float4* part4 = (float4*)bs;            // part[eg][128] viewed as float4
    part4[eg * 32 + lane] = make_float4(q[0], q[1], q[2], q[3]);
    __syncthreads();

    if (tid < BT) {
        float* part = bs;
        float s = 0.f;
#pragma unroll
        for (int g = 0; g < 8; g++) s += part[g * BT + tid];
        out[(size_t)(b0 + tid) * Odim + o] = expf(-s);
    }
}

extern "C" void kernel_launch(void* const* d_in, const int* in_sizes, int n_in,
                              void* d_out, int out_size) {
    const float* x       = (const float*)d_in[0];   // [8192, 64]
    const float* centers = (const float*)d_in[1];   // [256, 1, 64]
    const float* betas   = (const float*)d_in[2];   // [256, 64, 64]
    float* out = (float*)d_out;                     // [8192, 256]

    cproj_kernel<<<Odim, Ddim>>>(betas, centers);
    dim3 tg(Bdim / 32, Ddim / 32);
    xpose_kernel<<<tg, 256>>>(x);
    dim3 grid(Bdim / BT, Odim);
    ebf_main<<<grid, 256>>>(betas, out);
}

// round 10
// speedup vs baseline: 3.4425x; 2.3257x over previous
#include <cuda_runtime.h>
#include <cuda_bf16.h>
#include <math.h>
#include <stdint.h>

#define Bdim 8192
#define Ddim 64
#define Odim 256
#define BT   128

// ---------------- global scratch ----------------
// bf16 split operands
__device__ __align__(16) __nv_bfloat16 g_xs2[2 * Bdim * Ddim];          // [split][b][d]
__device__ __align__(16) __nv_bfloat16 g_bs2[Odim * 2 * Ddim * Ddim];   // [o][split][e][d]
__device__ float g_cproj[Odim * Ddim];

// ---------------- helpers ----------------
__device__ __forceinline__ unsigned smem_u32(const void* p) {
    unsigned a;
    asm("{ .reg .u64 t; cvta.to.shared.u64 t, %1; cvt.u32.u64 %0, t; }" : "=r"(a) : "l"(p));
    return a;
}

__device__ __forceinline__ void split2(float a, __nv_bfloat16& h, __nv_bfloat16& l) {
    h = __float2bfloat16(a);
    l = __float2bfloat16(a - __bfloat162float(h));
}

__device__ __forceinline__ void ldsm4(unsigned* r, unsigned addr) {
    asm volatile("ldmatrix.sync.aligned.m8n8.x4.shared.b16 {%0,%1,%2,%3}, [%4];"
                 : "=r"(r[0]), "=r"(r[1]), "=r"(r[2]), "=r"(r[3]) : "r"(addr));
}

__device__ __forceinline__ void mma16816(float* c, const unsigned* a, const unsigned* b) {
    asm volatile("mma.sync.aligned.m16n8k16.row.col.f32.bf16.bf16.f32 "
                 "{%0,%1,%2,%3}, {%4,%5,%6,%7}, {%8,%9}, {%0,%1,%2,%3};"
                 : "+f"(c[0]), "+f"(c[1]), "+f"(c[2]), "+f"(c[3])
                 : "r"(a[0]), "r"(a[1]), "r"(a[2]), "r"(a[3]), "r"(b[0]), "r"(b[1]));
}

// ---------------- prep: x -> 2 bf16 splits [split][b][d] ----------------
__global__ __launch_bounds__(256) void xsplit_kernel(const float* __restrict__ x) {
    int idx = blockIdx.x * 256 + threadIdx.x;   // 262144 = 8192*32
    int b = idx >> 5, dp = idx & 31;
    float2 v = *(const float2*)(x + b * Ddim + 2 * dp);
    __nv_bfloat16 h0, l0, h1, l1;
    split2(v.x, h0, l0);
    split2(v.y, h1, l1);
    __nv_bfloat162 hh; hh.x = h0; hh.y = h1;
    __nv_bfloat162 ll; ll.x = l0; ll.y = l1;
    *(__nv_bfloat162*)(g_xs2 + (size_t)b * Ddim + 2 * dp) = hh;
    *(__nv_bfloat162*)(g_xs2 + (size_t)(Bdim + b) * Ddim + 2 * dp) = ll;
}

// ---------------- prep: betas -> transposed splits [o][split][e][d] + cproj ----------------
// one block per o
__global__ __launch_bounds__(256) void bsplit_kernel(const float* __restrict__ betas,
                                                     const float* __restrict__ centers) {
    __shared__ float bsm[Ddim * Ddim];   // betas[o] as [d][e], 16 KB
    __shared__ float cs[Ddim];
    int o = blockIdx.x;
    int t = threadIdx.x;

    const float4* src = (const float4*)(betas + (size_t)o * Ddim * Ddim);
    float4* dst4 = (float4*)bsm;
#pragma unroll
    for (int i = 0; i < 4; i++) dst4[t + i * 256] = src[t + i * 256];
    if (t < Ddim) cs[t] = centers[o * Ddim + t];
    __syncthreads();

    // transposed splits: thread -> e = t>>2, d-group = t&3 (16 d's)
    {
        int e = t >> 2, dg = (t & 3) * 16;
        __nv_bfloat16* oh = g_bs2 + (size_t)o * 2 * Ddim * Ddim + (size_t)e * Ddim;
        __nv_bfloat16* ol = oh + Ddim * Ddim;
#pragma unroll
        for (int j = 0; j < 8; j++) {
            int d0 = dg + 2 * j;
            float v0 = bsm[d0 * Ddim + e];
            float v1 = bsm[(d0 + 1) * Ddim + e];
            __nv_bfloat16 h0, l0, h1, l1;
            split2(v0, h0, l0);
            split2(v1, h1, l1);
            __nv_bfloat162 hh; hh.x = h0; hh.y = h1;
            __nv_bfloat162 ll; ll.x = l0; ll.y = l1;
            *(__nv_bfloat162*)(oh + d0) = hh;
            *(__nv_bfloat162*)(ol + d0) = ll;
        }
    }
    // cproj[o][e] = sum_d betas[o][d][e] * centers[o][d]  (fp32 exact)
    if (t < Ddim) {
        float s = 0.f;
#pragma unroll 8
        for (int d = 0; d < Ddim; d++) s = fmaf(bsm[d * Ddim + t], cs[d], s);
        g_cproj[o * Ddim + t] = s;
    }
}

// ---------------- main mma.sync kernel ----------------
// smem: xs[2 splits][128 rows][72 bf16] (144B rows), bs[2][64][72], ncp[64]
#define XROW 144                 // bytes per padded row
#define SM_XS 0                  // 2 * 128 * 144 = 36864
#define SM_BS 36864              // 2 * 64 * 144 = 18432
#define SM_NCP 55296             // 64 floats
#define SM_TOTAL 55552

__global__ __launch_bounds__(128) void ebf_mma(float* __restrict__ out) {
    extern __shared__ __align__(16) unsigned char smem[];
    unsigned sb = smem_u32(smem);
    int tid = threadIdx.x;
    int lane = tid & 31, wid = tid >> 5;
    int o = blockIdx.x;
    int b0 = blockIdx.y * BT;

    // ---- stage x tile: 2 splits x 128 rows x 128B, padded to 144B rows ----
    {
        const float4* src = (const float4*)g_xs2;   // [2][8192][8] float4
#pragma unroll
        for (int i = 0; i < 16; i++) {
            int idx = tid + i * 128;
            int split = idx >> 10, row = (idx >> 3) & 127, c = idx & 7;
            float4 v = src[(size_t)split * (Bdim * 8) + (size_t)(b0 + row) * 8 + c];
            *(float4*)(smem + SM_XS + split * 18432 + row * XROW + c * 16) = v;
        }
    }
    // ---- stage beta tile: 2 splits x 64 rows x 128B ----
    {
        const float4* src = (const float4*)(g_bs2 + (size_t)o * 2 * Ddim * Ddim);
#pragma unroll
        for (int i = 0; i < 8; i++) {
            int idx = tid + i * 128;
            int split = idx >> 9, row = (idx >> 3) & 63, c = idx & 7;
            float4 v = src[idx];
            *(float4*)(smem + SM_BS + split * 9216 + row * XROW + c * 16) = v;
        }
    }
    if (tid < Ddim) ((float*)(smem + SM_NCP))[tid] = -g_cproj[o * Ddim + tid];
    __syncthreads();

    // ---- accumulators: warp covers m = 32*wid .. +31, n = 0..63 ----
    int m0 = 32 * wid;
    float acc[2][8][4];
    {
        const float* ncp = (const float*)(smem + SM_NCP);
#pragma unroll
        for (int s = 0; s < 8; s++) {
            float2 v = *(const float2*)(ncp + 8 * s + 2 * (lane & 3));
#pragma unroll
            for (int mi = 0; mi < 2; mi++) {
                acc[mi][s][0] = v.x; acc[mi][s][1] = v.y;
                acc[mi][s][2] = v.x; acc[mi][s][3] = v.y;
            }
        }
    }

    // ldmatrix base addresses
    // A (x): rows=b, k contiguous. x4 pattern: row = lane%16, chunk = lane/16
    unsigned abase = sb + SM_XS + (m0 + (lane & 15)) * XROW + (lane >> 4) * 16;
    // B (beta^T): rows=n(e), k contiguous. x4: groups (n0-7,k-lo)(n0-7,k-hi)(n8-15,k-lo)(n8-15,k-hi)
    unsigned bbase = sb + SM_BS + ((lane & 7) + ((lane >> 4) & 1) * 8) * XROW + ((lane >> 3) & 1) * 16;

    // ---- 3 split-products x 4 k-steps x 16 mma ----
#pragma unroll
    for (int p = 0; p < 3; p++) {
        int ai = (p == 2) ? 1 : 0;
        int bi = (p == 1) ? 1 : 0;
        unsigned ab = abase + ai * 18432;
        unsigned bb = bbase + bi * 9216;
#pragma unroll
        for (int k = 0; k < 4; k++) {
            unsigned A0[4], A1[4], Bf[4][4];
            ldsm4(A0, ab + k * 32);
            ldsm4(A1, ab + 16 * XROW + k * 32);
#pragma unroll
            for (int nn = 0; nn < 4; nn++) ldsm4(Bf[nn], bb + nn * 16 * XROW + k * 32);
#pragma unroll
            for (int nn = 0; nn < 4; nn++) {
                mma16816(acc[0][2 * nn],     A0, Bf[nn]);
                mma16816(acc[0][2 * nn + 1], A0, Bf[nn] + 2);
                mma16816(acc[1][2 * nn],     A1, Bf[nn]);
                mma16816(acc[1][2 * nn + 1], A1, Bf[nn] + 2);
            }
        }
    }

    // ---- epilogue: q = sum_e acc^2 per b-row; butterfly over the 4 lanes of a row ----
    float q[4];
#pragma unroll
    for (int mi = 0; mi < 2; mi++) {
        float qa = 0.f, qb = 0.f;
#pragma unroll
        for (int s = 0; s < 8; s++) {
            qa = fmaf(acc[mi][s][0], acc[mi][s][0], qa);
            qa = fmaf(acc[mi][s][1], acc[mi][s][1], qa);
            qb = fmaf(acc[mi][s][2], acc[mi][s][2], qb);
            qb = fmaf(acc[mi][s][3], acc[mi][s][3], qb);
        }
        q[2 * mi] = qa; q[2 * mi + 1] = qb;
    }
#pragma unroll
    for (int j = 0; j < 4; j++) {
        q[j] += __shfl_xor_sync(0xFFFFFFFFu, q[j], 1);
        q[j] += __shfl_xor_sync(0xFFFFFFFFu, q[j], 2);
    }
    if ((lane & 3) == 0) {
        int r = lane >> 2;                       // 0..7
        int bg = b0 + m0 + r;
        out[(size_t)(bg)      * Odim + o] = expf(-q[0]);
        out[(size_t)(bg + 8)  * Odim + o] = expf(-q[1]);
        out[(size_t)(bg + 16) * Odim + o] = expf(-q[2]);
        out[(size_t)(bg + 24) * Odim + o] = expf(-q[3]);
    }
}

// ---------------- launch ----------------
extern "C" void kernel_launch(void* const* d_in, const int* in_sizes, int n_in,
                              void* d_out, int out_size) {
    const float* x       = (const float*)d_in[0];   // [8192, 64]
    const float* centers = (const float*)d_in[1];   // [256, 1, 64]
    const float* betas   = (const float*)d_in[2];   // [256, 64, 64]
    float* out = (float*)d_out;                     // [8192, 256]

    cudaFuncSetAttribute(ebf_mma, cudaFuncAttributeMaxDynamicSharedMemorySize, SM_TOTAL);

    xsplit_kernel<<<(Bdim * 32) / 256, 256>>>(x);
    bsplit_kernel<<<Odim, 256>>>(betas, centers);
    dim3 grid(Odim, Bdim / BT);                     // o fastest -> x-tile reuse
    ebf_mma<<<grid, 128, SM_TOTAL>>>(out);
}

// round 12
// speedup vs baseline: 3.8302x; 1.1126x over previous
#include <cuda_runtime.h>
#include <cuda_bf16.h>
#include <math.h>
#include <stdint.h>

#define Bdim 8192
#define Ddim 64
#define Odim 256

// ---------------- global scratch ----------------
__device__ __align__(16) __nv_bfloat16 g_xs2[2 * Bdim * Ddim];          // [split][b][d]
__device__ __align__(16) __nv_bfloat16 g_bs2[Odim * 2 * Ddim * Ddim];   // [o][split][e][d]
__device__ float g_cproj[Odim * Ddim];

// ---------------- helpers ----------------
__device__ __forceinline__ unsigned smem_u32(const void* p) {
    unsigned a;
    asm("{ .reg .u64 t; cvta.to.shared.u64 t, %1; cvt.u32.u64 %0, t; }" : "=r"(a) : "l"(p));
    return a;
}
__device__ __forceinline__ void split2(float a, __nv_bfloat16& h, __nv_bfloat16& l) {
    h = __float2bfloat16(a);
    l = __float2bfloat16(a - __bfloat162float(h));
}
__device__ __forceinline__ void ldsm4(unsigned* r, unsigned addr) {
    asm volatile("ldmatrix.sync.aligned.m8n8.x4.shared.b16 {%0,%1,%2,%3}, [%4];"
                 : "=r"(r[0]), "=r"(r[1]), "=r"(r[2]), "=r"(r[3]) : "r"(addr));
}
__device__ __forceinline__ void mma16816(float* c, const unsigned* a, const unsigned* b) {
    asm volatile("mma.sync.aligned.m16n8k16.row.col.f32.bf16.bf16.f32 "
                 "{%0,%1,%2,%3}, {%4,%5,%6,%7}, {%8,%9}, {%0,%1,%2,%3};"
                 : "+f"(c[0]), "+f"(c[1]), "+f"(c[2]), "+f"(c[3])
                 : "r"(a[0]), "r"(a[1]), "r"(a[2]), "r"(a[3]), "r"(b[0]), "r"(b[1]));
}
#define CP_ASYNC16(dst, src) \
    asm volatile("cp.async.cg.shared.global [%0], [%1], 16;" :: "r"(dst), "l"(src) : "memory")
#define CP_COMMIT() asm volatile("cp.async.commit_group;" ::: "memory")
#define CP_WAIT1()  asm volatile("cp.async.wait_group 1;" ::: "memory")
#define CP_WAIT0()  asm volatile("cp.async.wait_group 0;" ::: "memory")

// ---------------- prep kernels (unchanged from R10) ----------------
__global__ __launch_bounds__(256) void xsplit_kernel(const float* __restrict__ x) {
    int idx = blockIdx.x * 256 + threadIdx.x;
    int b = idx >> 5, dp = idx & 31;
    float2 v = *(const float2*)(x + b * Ddim + 2 * dp);
    __nv_bfloat16 h0, l0, h1, l1;
    split2(v.x, h0, l0);
    split2(v.y, h1, l1);
    __nv_bfloat162 hh; hh.x = h0; hh.y = h1;
    __nv_bfloat162 ll; ll.x = l0; ll.y = l1;
    *(__nv_bfloat162*)(g_xs2 + (size_t)b * Ddim + 2 * dp) = hh;
    *(__nv_bfloat162*)(g_xs2 + (size_t)(Bdim + b) * Ddim + 2 * dp) = ll;
}

__global__ __launch_bounds__(256) void bsplit_kernel(const float* __restrict__ betas,
                                                     const float* __restrict__ centers) {
    __shared__ float bsm[Ddim * Ddim];
    __shared__ float cs[Ddim];
    int o = blockIdx.x;
    int t = threadIdx.x;
    const float4* src = (const float4*)(betas + (size_t)o * Ddim * Ddim);
    float4* dst4 = (float4*)bsm;
#pragma unroll
    for (int i = 0; i < 4; i++) dst4[t + i * 256] = src[t + i * 256];
    if (t < Ddim) cs[t] = centers[o * Ddim + t];
    __syncthreads();
    {
        int e = t >> 2, dg = (t & 3) * 16;
        __nv_bfloat16* oh = g_bs2 + (size_t)o * 2 * Ddim * Ddim + (size_t)e * Ddim;
        __nv_bfloat16* ol = oh + Ddim * Ddim;
#pragma unroll
        for (int j = 0; j < 8; j++) {
            int d0 = dg + 2 * j;
            float v0 = bsm[d0 * Ddim + e];
            float v1 = bsm[(d0 + 1) * Ddim + e];
            __nv_bfloat16 h0, l0, h1, l1;
            split2(v0, h0, l0);
            split2(v1, h1, l1);
            __nv_bfloat162 hh; hh.x = h0; hh.y = h1;
            __nv_bfloat162 ll; ll.x = l0; ll.y = l1;
            *(__nv_bfloat162*)(oh + d0) = hh;
            *(__nv_bfloat162*)(ol + d0) = ll;
        }
    }
    if (t < Ddim) {
        float s = 0.f;
#pragma unroll 8
        for (int d = 0; d < Ddim; d++) s = fmaf(bsm[d * Ddim + t], cs[d], s);
        g_cproj[o * Ddim + t] = s;
    }
}

// ---------------- main kernel ----------------
#define XROW 144
#define MT 64                    // rows per b-tile
#define TPB 8                    // tiles per block
#define XBUF 9216                // 64 rows * 144
#define SM_X0 0                  // buf0: 2 splits * 9216 = 18432
#define SM_X1 18432
#define SM_BS 36864              // 2 splits * 128 n-rows * 144 = 36864
#define SM_NCP 73728             // 128 floats
#define SM_PART 74240            // 4 * 64 floats
#define SM_TOTAL 75264

__device__ __forceinline__ void stage_x(unsigned sb_buf, int b0, int tid) {
    const unsigned char* xg = (const unsigned char*)g_xs2;
#pragma unroll
    for (int i = 0; i < 8; i++) {
        int idx = tid + i * 128;
        int split = idx >> 9, row = (idx >> 3) & 63, c = idx & 7;
        unsigned dst = sb_buf + split * XBUF + row * XROW + c * 16;
        const unsigned char* src = xg + (size_t)split * (Bdim * Ddim * 2)
                                      + (size_t)(b0 + row) * (Ddim * 2) + c * 16;
        CP_ASYNC16(dst, src);
    }
    CP_COMMIT();
}

__global__ __launch_bounds__(128) void ebf_mma(float* __restrict__ out) {
    extern __shared__ __align__(16) unsigned char smem[];
    unsigned sb = smem_u32(smem);
    int tid = threadIdx.x;
    int lane = tid & 31, wid = tid >> 5;
    int op = blockIdx.x;             // o-pair
    int o0 = op * 2;
    int chunk = blockIdx.y;          // b-chunk
    int bbase0 = chunk * (MT * TPB);

    // ---- stage beta o-pair: smem [split][n=ol*64+e][144B] ----
    {
        const float4* src = (const float4*)(g_bs2 + (size_t)o0 * 2 * Ddim * Ddim);
#pragma unroll
        for (int i = 0; i < 16; i++) {
            int idx = tid + i * 128;           // 2048 float4
            int c = idx & 7, e = (idx >> 3) & 63, s = (idx >> 9) & 1, ol = idx >> 10;
            float4 v = src[(size_t)(ol * 2 + s) * 512 + e * 8 + c];
            *(float4*)(smem + SM_BS + s * 18432 + (ol * 64 + e) * XROW + c * 16) = v;
        }
    }
    ((float*)(smem + SM_NCP))[tid] = -g_cproj[(o0 + (tid >> 6)) * Ddim + (tid & 63)];

    // prefetch x tiles 0,1
    stage_x(sb + SM_X0, bbase0, tid);
    stage_x(sb + SM_X1, bbase0 + MT, tid);
    __syncthreads();

    // ---- load B fragments once: Breg[split][k][npair][4] ----
    int n0 = wid * 32;
    unsigned Breg[2][4][2][4];
#pragma unroll
    for (int s = 0; s < 2; s++)
#pragma unroll
        for (int k = 0; k < 4; k++)
#pragma unroll
            for (int np = 0; np < 2; np++) {
                unsigned addr = sb + SM_BS + s * 18432
                    + (n0 + (lane & 7) + ((lane >> 4) & 1) * 8 + np * 16) * XROW
                    + ((lane >> 3) & 1) * 16 + k * 32;
                ldsm4(Breg[s][k][np], addr);
            }

    const float* ncp = (const float*)(smem + SM_NCP);
    float* part = (float*)(smem + SM_PART);

    for (int j = 0; j < TPB; j++) {
        if (j < TPB - 1) { CP_WAIT1(); } else { CP_WAIT0(); }
        __syncthreads();
        unsigned xbuf = sb + ((j & 1) ? SM_X1 : SM_X0);

        // ---- init acc to -cproj ----
        float acc[4][4][4];   // [mi][ns(n8)][4]
#pragma unroll
        for (int ns = 0; ns < 4; ns++) {
            float2 v = *(const float2*)(ncp + n0 + ns * 8 + 2 * (lane & 3));
#pragma unroll
            for (int mi = 0; mi < 4; mi++) {
                acc[mi][ns][0] = v.x; acc[mi][ns][1] = v.y;
                acc[mi][ns][2] = v.x; acc[mi][ns][3] = v.y;
            }
        }

        // ---- mma: 4 k-steps x { load Ah,Al ; 3 products } ----
        unsigned abase = xbuf + (lane & 15) * XROW + (lane >> 4) * 16;
#pragma unroll
        for (int k = 0; k < 4; k++) {
            unsigned Ah[4][4], Al[4][4];
#pragma unroll
            for (int mi = 0; mi < 4; mi++) {
                ldsm4(Ah[mi], abase + mi * 16 * XROW + k * 32);
                ldsm4(Al[mi], abase + XBUF + mi * 16 * XROW + k * 32);
            }
#pragma unroll
            for (int mi = 0; mi < 4; mi++) {
#pragma unroll
                for (int np = 0; np < 2; np++) {
                    // (xh, bh)
                    mma16816(acc[mi][2 * np],     Ah[mi], Breg[0][k][np]);
                    mma16816(acc[mi][2 * np + 1], Ah[mi], Breg[0][k][np] + 2);
                    // (xh, bl)
                    mma16816(acc[mi][2 * np],     Ah[mi], Breg[1][k][np]);
                    mma16816(acc[mi][2 * np + 1], Ah[mi], Breg[1][k][np] + 2);
                    // (xl, bh)
                    mma16816(acc[mi][2 * np],     Al[mi], Breg[0][k][np]);
                    mma16816(acc[mi][2 * np + 1], Al[mi], Breg[0][k][np] + 2);
                }
            }
        }

        // ---- epilogue: row sums of squares over this warp's 32 e's ----
#pragma unroll
        for (int mi = 0; mi < 4; mi++) {
            float qa = 0.f, qb = 0.f;
#pragma unroll
            for (int ns = 0; ns < 4; ns++) {
                qa = fmaf(acc[mi][ns][0], acc[mi][ns][0], qa);
                qa = fmaf(acc[mi][ns][1], acc[mi][ns][1], qa);
                qb = fmaf(acc[mi][ns][2], acc[mi][ns][2], qb);
                qb = fmaf(acc[mi][ns][3], acc[mi][ns][3], qb);
            }
            qa += __shfl_xor_sync(0xFFFFFFFFu, qa, 1);
            qa += __shfl_xor_sync(0xFFFFFFFFu, qa, 2);
            qb += __shfl_xor_sync(0xFFFFFFFFu, qb, 1);
            qb += __shfl_xor_sync(0xFFFFFFFFu, qb, 2);
            if ((lane & 3) == 0) {
                int r = lane >> 2;
                part[wid * 64 + mi * 16 + r]     = qa;
                part[wid * 64 + mi * 16 + r + 8] = qb;
            }
        }
        __syncthreads();

        int b0 = bbase0 + j * MT;
        if (tid < MT) {
            float s0 = part[0 * 64 + tid] + part[1 * 64 + tid];
            float s1 = part[2 * 64 + tid] + part[3 * 64 + tid];
            float2 r = make_float2(__expf(-s0), __expf(-s1));
            *(float2*)(out + (size_t)(b0 + tid) * Odim + o0) = r;
        }
        __syncthreads();   // all warps past part + ldsm before buffer reuse

        if (j + 2 < TPB)
            stage_x(sb + ((j & 1) ? SM_X1 : SM_X0), bbase0 + (j + 2) * MT, tid);
    }
}

// ---------------- launch ----------------
extern "C" void kernel_launch(void* const* d_in, const int* in_sizes, int n_in,
                              void* d_out, int out_size) {
    const float* x       = (const float*)d_in[0];   // [8192, 64]
    const float* centers = (const float*)d_in[1];   // [256, 1, 64]
    const float* betas   = (const float*)d_in[2];   // [256, 64, 64]
    float* out = (float*)d_out;                     // [8192, 256]

    cudaFuncSetAttribute(ebf_mma, cudaFuncAttributeMaxDynamicSharedMemorySize, SM_TOTAL);

    xsplit_kernel<<<(Bdim * 32) / 256, 256>>>(x);
    bsplit_kernel<<<Odim, 256>>>(betas, centers);
    dim3 grid(Odim / 2, Bdim / (MT * TPB));         // 128 x 16 = 2048 blocks
    ebf_mma<<<grid, 128, SM_TOTAL>>>(out);
}